// round 7
// baseline (speedup 1.0000x reference)
#include <cuda_runtime.h>
#include <cuda_fp16.h>
#include <math.h>
#include <stdint.h>

// Problem constants
#define N0c 585728
#define N1c 22528
#define N2c 2048
#define E1c 563200
#define E2c 20480
#define INC 602
#define HIDc 256
#define OUTC 41
#define KPAD 640            // per-operand K padded
#define KPAD2 1280          // concatenated K
#define BKc 64              // GEMM K tile
#define NITER (KPAD2 / BKc) // 20

// ---------------- scratch (device globals; no allocation allowed) ----------
__device__ int    g_is64;
__device__ int    g_cnt1[N1c];
__device__ int    g_off1[N1c];
__device__ int    g_cur1[N1c];
__device__ int    g_srt1[E1c];
__device__ __half g_acat[(size_t)N1c * KPAD2];  // [agg | x] fp16, 57.7 MB
__device__ __half g_bcat[(size_t)HIDc * KPAD2]; // [Wl;Wr]^T as [N=256][K=1280] fp16
__device__ float  g_h[(size_t)N1c * HIDc];      // 23 MB hidden (fp32)
__device__ int    g_cnt2[N2c];
__device__ int    g_off2[N2c];
__device__ int    g_cur2[N2c];
__device__ int    g_srt2[E2c];
__device__ float  g_agg2[(size_t)N2c * HIDc];   // 2 MB

// ======================= PTX helpers =======================================
__device__ __forceinline__ uint32_t smem_u32(const void* p) {
    uint32_t a;
    asm("{ .reg .u64 t; cvta.to.shared.u64 t, %1; cvt.u32.u64 %0, t; }" : "=r"(a) : "l"(p));
    return a;
}
#define CP_ASYNC16(sa, g) \
    asm volatile("cp.async.cg.shared.global [%0], [%1], 16;" :: "r"((uint32_t)(sa)), "l"(g))
#define CP_ASYNC_COMMIT() asm volatile("cp.async.commit_group;" ::: "memory")
#define CP_ASYNC_WAIT(n) asm volatile("cp.async.wait_group %0;" :: "n"(n) : "memory")
#define SWZ128(o) ((o) ^ (((o) >> 3) & 0x70))

__device__ __forceinline__ void ldsm_x4(uint32_t& r0, uint32_t& r1, uint32_t& r2,
                                        uint32_t& r3, uint32_t a) {
    asm volatile("ldmatrix.sync.aligned.m8n8.x4.shared.b16 {%0,%1,%2,%3}, [%4];"
                 : "=r"(r0), "=r"(r1), "=r"(r2), "=r"(r3) : "r"(a));
}
__device__ __forceinline__ void mma_16816(float* c, const uint32_t* a, const uint32_t* b) {
    asm volatile("mma.sync.aligned.m16n8k16.row.col.f32.f16.f16.f32 "
                 "{%0,%1,%2,%3}, {%4,%5,%6,%7}, {%8,%9}, {%0,%1,%2,%3};"
                 : "+f"(c[0]), "+f"(c[1]), "+f"(c[2]), "+f"(c[3])
                 : "r"(a[0]), "r"(a[1]), "r"(a[2]), "r"(a[3]), "r"(b[0]), "r"(b[1]));
}

__device__ __forceinline__ int edge_at(const void* ei, int E, int which, int e, int is64) {
    if (is64) return (int)((const long long*)ei)[(size_t)which * E + e];
    return ((const int*)ei)[(size_t)which * E + e];
}

// ---------------- zero histograms + dtype detect ------------------------------
__global__ void k_zero(const int* __restrict__ e1) {
    int i = blockIdx.x * blockDim.x + threadIdx.x;
    if (i == 0) {
        int nz = 0;
        for (int s = 1; s < 256; s += 2) nz += (e1[s] != 0);
        g_is64 = (nz == 0) ? 1 : 0;
    }
    if (i < N1c) g_cnt1[i] = 0;
    if (i < N2c) g_cnt2[i] = 0;
}

// ---------------- histogram of dst (both layers, one launch) ------------------
__global__ void k_count_all(const void* __restrict__ ei1, const void* __restrict__ ei2) {
    int e = blockIdx.x * blockDim.x + threadIdx.x;
    int is64 = g_is64;
    if (e < E1c) atomicAdd(&g_cnt1[edge_at(ei1, E1c, 1, e, is64)], 1);
    if (e < E2c) atomicAdd(&g_cnt2[edge_at(ei2, E2c, 1, e, is64)], 1);
}

// ---------------- thread-coarsened exclusive scan (block 0: L1, block 1: L2) --
__global__ void k_scan_all() {
    __shared__ int s[1024];
    const int CH = 22;
    const int* cnt = blockIdx.x == 0 ? g_cnt1 : g_cnt2;
    int* off = blockIdx.x == 0 ? g_off1 : g_off2;
    int* cur = blockIdx.x == 0 ? g_cur1 : g_cur2;
    int n = blockIdx.x == 0 ? N1c : N2c;
    int t = threadIdx.x;
    int base = t * CH;
    int loc[CH];
    int sum = 0;
#pragma unroll
    for (int j = 0; j < CH; j++) {
        int i = base + j;
        int v = (i < n) ? cnt[i] : 0;
        loc[j] = sum;
        sum += v;
    }
    s[t] = sum;
    __syncthreads();
#pragma unroll
    for (int st = 1; st < 1024; st <<= 1) {
        int v = (t >= st) ? s[t - st] : 0;
        __syncthreads();
        s[t] += v;
        __syncthreads();
    }
    int tbase = (t > 0) ? s[t - 1] : 0;
#pragma unroll
    for (int j = 0; j < CH; j++) {
        int i = base + j;
        if (i < n) { int e = tbase + loc[j]; off[i] = e; cur[i] = e; }
    }
}

// ---------------- scatter src ids into dst-sorted order (both layers) ---------
__global__ void k_scatter_all(const void* __restrict__ ei1, const void* __restrict__ ei2) {
    int e = blockIdx.x * blockDim.x + threadIdx.x;
    int is64 = g_is64;
    if (e < E1c) {
        int sr = edge_at(ei1, E1c, 0, e, is64);
        int d = edge_at(ei1, E1c, 1, e, is64);
        g_srt1[atomicAdd(&g_cur1[d], 1)] = sr;
    }
    if (e < E2c) {
        int sr = edge_at(ei2, E2c, 0, e, is64);
        int d = edge_at(ei2, E2c, 1, e, is64);
        g_srt2[atomicAdd(&g_cur2[d], 1)] = sr;
    }
}

// ---------------- layer-1 mean aggregation + x conversion -> acat ------------
// Block = one dst row. float2 gather (301 per row). Also converts x[row] into
// acat[row][640:1242] (fused prep_x).
__global__ void __launch_bounds__(256)
k_aggregate1(const float* __restrict__ X, const int* __restrict__ off,
             const int* __restrict__ cnt, const int* __restrict__ srt,
             __half* __restrict__ acat) {
    __shared__ int s_src[256];
    const int row = blockIdx.x;
    const int t = threadIdx.x;
    const int beg = off[row], deg = cnt[row];
    float2 a0 = make_float2(0.f, 0.f), a1 = make_float2(0.f, 0.f);
    for (int t0 = 0; t0 < deg; t0 += 256) {
        int nn = min(256, deg - t0);
        __syncthreads();
        if (t < nn) s_src[t] = srt[beg + t0 + t];
        __syncthreads();
#pragma unroll 2
        for (int i = 0; i < nn; i++) {
            const float2* xr = (const float2*)(X + (size_t)s_src[i] * INC);
            float2 v0 = __ldg(xr + t);
            a0.x += v0.x; a0.y += v0.y;
            if (t < 45) {
                float2 v1 = __ldg(xr + t + 256);
                a1.x += v1.x; a1.y += v1.y;
            }
        }
    }
    float inv = deg > 0 ? 1.f / (float)deg : 0.f;
    __half2* ar = (__half2*)(acat + (size_t)row * KPAD2);
    ar[t] = __floats2half2_rn(a0.x * inv, a0.y * inv);
    if (t < 45) ar[t + 256] = __floats2half2_rn(a1.x * inv, a1.y * inv);
    else if (t + 256 < 320) ar[t + 256] = __floats2half2_rn(0.f, 0.f);

    // fused x[row] -> fp16 into second half
    const float2* xr = (const float2*)(X + (size_t)row * INC);
    __half2* xh = ar + 320;
    float2 v = __ldg(xr + t);
    xh[t] = __floats2half2_rn(v.x, v.y);
    if (t < 45) {
        float2 v1 = __ldg(xr + t + 256);
        xh[t + 256] = __floats2half2_rn(v1.x, v1.y);
    } else if (t + 256 < 320) {
        xh[t + 256] = __floats2half2_rn(0.f, 0.f);
    }
}

// ---------------- weight conversion -> bcat [N=256][K=1280] -------------------
__global__ void k_prep_w(const float* __restrict__ Wl, const float* __restrict__ Wr,
                         __half* __restrict__ bcat) {
    int n = blockIdx.x;  // 0..255
    __half* br = bcat + (size_t)n * KPAD2;
    for (int k = threadIdx.x; k < KPAD2; k += blockDim.x) {
        float v = 0.f;
        if (k < INC) v = Wl[(size_t)k * HIDc + n];
        else if (k >= KPAD && k < KPAD + INC) v = Wr[(size_t)(k - KPAD) * HIDc + n];
        br[k] = __float2half_rn(v);
    }
}

// ---------------- layer-1 GEMM via mma.sync (fp16 in, fp32 acc) --------------
// H[M,256] = relu(acat[M,1280] @ bcat^T + bias).
// BM=128, BN=128, BK=64; 8 warps (4 m x 2 n), warp tile 32x64.
#define A_STAGE 16384            // 128 rows * 128 B
#define B_STAGE 16384            // 128 rows * 128 B
#define GSMEM (2 * A_STAGE + 2 * B_STAGE)   // 64 KB
__global__ void __launch_bounds__(256)
k_gemm1_mma(const __half* __restrict__ A, const __half* __restrict__ B,
            const float* __restrict__ bias, float* __restrict__ H) {
    extern __shared__ char sm[];
    const uint32_t sA = smem_u32(sm);
    const uint32_t sB = sA + 2 * A_STAGE;
    const int tid = threadIdx.x;
    const int lane = tid & 31, wid = tid >> 5;
    const int m0 = blockIdx.x * 128;
    const int n0 = blockIdx.y * 128;
    const int wm = (wid & 3) * 32;       // warp m offset
    const int wn = (wid >> 2) * 64;      // warp n offset

    auto load_stage = [&](int it, int buf) {
        const size_t kbase = (size_t)it * BKc;
#pragma unroll
        for (int r = 0; r < 4; r++) {            // A: 1024 units of 16B
            int u = tid + r * 256;
            int row = u >> 3, un = u & 7;
            uint32_t so = SWZ128((uint32_t)(row * 128 + un * 16));
            const __half* g = A + (size_t)(m0 + row) * KPAD2 + kbase + un * 8;
            CP_ASYNC16(sA + buf * A_STAGE + so, (const char*)g);
        }
#pragma unroll
        for (int r = 0; r < 4; r++) {            // B: 1024 units of 16B
            int u = tid + r * 256;
            int row = u >> 3, un = u & 7;
            uint32_t so = SWZ128((uint32_t)(row * 128 + un * 16));
            const __half* g = B + (size_t)(n0 + row) * KPAD2 + kbase + un * 8;
            CP_ASYNC16(sB + buf * B_STAGE + so, (const char*)g);
        }
        CP_ASYNC_COMMIT();
    };

    // precomputed swizzled ldmatrix addresses (buf 0)
    uint32_t a_addr[2][4], b_addr[4][4];
#pragma unroll
    for (int mi = 0; mi < 2; mi++)
#pragma unroll
        for (int ks = 0; ks < 4; ks++) {
            int row = wm + mi * 16 + (lane & 15);
            int col = ks * 32 + ((lane >> 4) & 1) * 16;
            a_addr[mi][ks] = sA + SWZ128((uint32_t)(row * 128 + col));
        }
#pragma unroll
    for (int p = 0; p < 4; p++)
#pragma unroll
        for (int ks = 0; ks < 4; ks++) {
            int row = wn + p * 16 + ((lane >> 4) & 1) * 8 + (lane & 7);
            int col = ks * 32 + ((lane >> 3) & 1) * 16;
            b_addr[p][ks] = sB + SWZ128((uint32_t)(row * 128 + col));
        }

    float acc[2][8][4];
#pragma unroll
    for (int i = 0; i < 2; i++)
#pragma unroll
        for (int j = 0; j < 8; j++)
#pragma unroll
            for (int q = 0; q < 4; q++) acc[i][j][q] = 0.f;

    load_stage(0, 0);
    for (int it = 0; it < NITER; it++) {
        int buf = it & 1;
        if (it + 1 < NITER) {
            load_stage(it + 1, (it + 1) & 1);
            CP_ASYNC_WAIT(1);
        } else {
            CP_ASYNC_WAIT(0);
        }
        __syncthreads();

        uint32_t aoff = buf * A_STAGE, boff = buf * B_STAGE;
#pragma unroll
        for (int ks = 0; ks < 4; ks++) {
            uint32_t af[2][4];
#pragma unroll
            for (int mi = 0; mi < 2; mi++)
                ldsm_x4(af[mi][0], af[mi][1], af[mi][2], af[mi][3], a_addr[mi][ks] + aoff);
            uint32_t bf[8][2];
#pragma unroll
            for (int p = 0; p < 4; p++) {
                uint32_t r0, r1, r2, r3;
                ldsm_x4(r0, r1, r2, r3, b_addr[p][ks] + boff);
                bf[p * 2 + 0][0] = r0; bf[p * 2 + 0][1] = r1;
                bf[p * 2 + 1][0] = r2; bf[p * 2 + 1][1] = r3;
            }
#pragma unroll
            for (int mi = 0; mi < 2; mi++)
#pragma unroll
                for (int ni = 0; ni < 8; ni++)
                    mma_16816(acc[mi][ni], af[mi], bf[ni]);
        }
        __syncthreads();
    }

    // epilogue: bias + ReLU, write fp32 H
#pragma unroll
    for (int mi = 0; mi < 2; mi++) {
#pragma unroll
        for (int ni = 0; ni < 8; ni++) {
            int col = n0 + wn + ni * 8 + (lane & 3) * 2;
            float b0 = __ldg(bias + col), b1 = __ldg(bias + col + 1);
            int r0 = m0 + wm + mi * 16 + (lane >> 2);
            float2 o0, o1;
            o0.x = fmaxf(acc[mi][ni][0] + b0, 0.f);
            o0.y = fmaxf(acc[mi][ni][1] + b1, 0.f);
            o1.x = fmaxf(acc[mi][ni][2] + b0, 0.f);
            o1.y = fmaxf(acc[mi][ni][3] + b1, 0.f);
            *(float2*)&H[(size_t)r0 * HIDc + col] = o0;
            *(float2*)&H[(size_t)(r0 + 8) * HIDc + col] = o1;
        }
    }
}

// ---------------- layer-2 mean aggregation (fp32) ----------------------------
__global__ void k_aggregate2(const float* __restrict__ X, const int* __restrict__ off,
                             const int* __restrict__ cnt, const int* __restrict__ srt,
                             float* __restrict__ agg) {
    __shared__ int s_src[256];
    int row = blockIdx.x;
    int beg = off[row], deg = cnt[row];
    float acc = 0.f;
    for (int t0 = 0; t0 < deg; t0 += 256) {
        int nn = min(256, deg - t0);
        __syncthreads();
        if ((int)threadIdx.x < nn) s_src[threadIdx.x] = srt[beg + t0 + threadIdx.x];
        __syncthreads();
#pragma unroll 4
        for (int i = 0; i < nn; i++)
            acc += __ldg(X + (size_t)s_src[i] * HIDc + threadIdx.x);
    }
    float inv = deg > 0 ? 1.f / (float)deg : 0.f;
    agg[(size_t)row * HIDc + threadIdx.x] = acc * inv;
}

// ---------------- layer-2 GEMM + bias + log_softmax --------------------------
__global__ void k_out(const float* __restrict__ Wl2, const float* __restrict__ Wr2,
                      const float* __restrict__ bl2, float* __restrict__ out) {
    __shared__ float sa[HIDc];
    __shared__ float sh[HIDc];
    __shared__ float vals[OUTC];
    __shared__ float s_max, s_lse;
    int r = blockIdx.x;
    for (int c = threadIdx.x; c < HIDc; c += blockDim.x) {
        sa[c] = g_agg2[(size_t)r * HIDc + c];
        sh[c] = g_h[(size_t)r * HIDc + c];
    }
    __syncthreads();
    int n = threadIdx.x;
    if (n < OUTC) {
        float acc = bl2[n];
#pragma unroll 4
        for (int k = 0; k < HIDc; k++)
            acc += sa[k] * Wl2[k * OUTC + n] + sh[k] * Wr2[k * OUTC + n];
        vals[n] = acc;
    }
    __syncthreads();
    if (threadIdx.x == 0) {
        float mx = -1e30f;
        for (int i = 0; i < OUTC; i++) mx = fmaxf(mx, vals[i]);
        float s = 0.f;
        for (int i = 0; i < OUTC; i++) s += expf(vals[i] - mx);
        s_max = mx;
        s_lse = logf(s);
    }
    __syncthreads();
    if (n < OUTC) out[(size_t)r * OUTC + n] = vals[n] - s_max - s_lse;
}

// ---------------- launch -----------------------------------------------------
extern "C" void kernel_launch(void* const* d_in, const int* in_sizes, int n_in,
                              void* d_out, int out_size) {
    const float* x   = (const float*)d_in[0];
    const void*  ei1 = d_in[1];
    const void*  ei2 = d_in[2];
    const float* Wl1 = (const float*)d_in[3];
    const float* bl1 = (const float*)d_in[4];
    const float* Wr1 = (const float*)d_in[5];
    const float* Wl2 = (const float*)d_in[6];
    const float* bl2 = (const float*)d_in[7];
    const float* Wr2 = (const float*)d_in[8];
    float* out = (float*)d_out;

    cudaFuncSetAttribute(k_gemm1_mma, cudaFuncAttributeMaxDynamicSharedMemorySize, GSMEM);

    void *p_off1, *p_cnt1, *p_srt1, *p_acat, *p_bcat, *p_h;
    void *p_off2, *p_cnt2, *p_srt2, *p_agg2;
    cudaGetSymbolAddress(&p_off1, g_off1);
    cudaGetSymbolAddress(&p_cnt1, g_cnt1);
    cudaGetSymbolAddress(&p_srt1, g_srt1);
    cudaGetSymbolAddress(&p_acat, g_acat);
    cudaGetSymbolAddress(&p_bcat, g_bcat);
    cudaGetSymbolAddress(&p_h,    g_h);
    cudaGetSymbolAddress(&p_off2, g_off2);
    cudaGetSymbolAddress(&p_cnt2, g_cnt2);
    cudaGetSymbolAddress(&p_srt2, g_srt2);
    cudaGetSymbolAddress(&p_agg2, g_agg2);

    k_zero<<<(N1c + 255) / 256, 256>>>((const int*)ei1);
    k_count_all<<<(E1c + 255) / 256, 256>>>(ei1, ei2);
    k_scan_all<<<2, 1024>>>();
    k_scatter_all<<<(E1c + 255) / 256, 256>>>(ei1, ei2);

    // weight conversion (independent of aggregation)
    k_prep_w<<<HIDc, 256>>>(Wl1, Wr1, (__half*)p_bcat);

    // layer-1 mean aggregation + fused x conversion -> acat
    k_aggregate1<<<N1c, 256>>>(x, (const int*)p_off1, (const int*)p_cnt1,
                               (const int*)p_srt1, (__half*)p_acat);

    // layer-1 fused dual GEMM + bias + ReLU via mma.sync -> g_h (fp32)
    dim3 gg(N1c / 128, HIDc / 128);
    k_gemm1_mma<<<gg, 256, GSMEM>>>((const __half*)p_acat, (const __half*)p_bcat,
                                    bl1, (float*)p_h);

    // layer-2 mean aggregation of 256-dim h rows
    k_aggregate2<<<N2c, 256>>>((const float*)p_h, (const int*)p_off2,
                               (const int*)p_cnt2, (const int*)p_srt2, (float*)p_agg2);

    // layer-2 GEMM + bias + log_softmax
    k_out<<<N2c, 64>>>(Wl2, Wr2, bl2, out);
}